// round 1
// baseline (speedup 1.0000x reference)
#include <cuda_runtime.h>

#define Nn   10000
#define Ne   320000
#define EAt  330000      // edges + self loops
#define HID  256
#define ENC_NEG_INF 0x007FFFFFu   // encoded -inf for float-ordered atomicMax

// ---------------- scratch (static device globals; no allocation) ----------------
__device__ float    g_deg[Nn];
__device__ float    g_loop[Nn];
__device__ float    g_xl[Nn*HID];
__device__ float    g_xr[Nn*HID];
__device__ float    g_acc[Nn*HID];
__device__ float    g_h[Nn*HID];
__device__ float    g_logit[EAt*4];
__device__ unsigned g_mx[Nn*4];
__device__ float    g_den[Nn*4];
__device__ float    g_p1[Nn*128];
__device__ float    g_pl[Nn*4];
__device__ float    g_red[2];

// ---------------- helpers ----------------
__device__ __forceinline__ unsigned encf(float f){
    unsigned u = __float_as_uint(f);
    return (u & 0x80000000u) ? ~u : (u | 0x80000000u);
}
__device__ __forceinline__ float decf(unsigned u){
    return (u & 0x80000000u) ? __uint_as_float(u & 0x7FFFFFFFu) : __uint_as_float(~u);
}
__device__ __forceinline__ float lrelu(float v){ return v > 0.f ? v : 0.2f * v; }

// vector f32 reduction-add to global (sm_90+): 4x fewer L2 atomic ops
__device__ __forceinline__ void red4(float* p, float a, float b, float c, float d){
    asm volatile("red.global.add.v4.f32 [%0], {%1,%2,%3,%4};"
                 :: "l"(p), "f"(a), "f"(b), "f"(c), "f"(d) : "memory");
}

__device__ __forceinline__ float dot8(float4 l0, float4 l1, float4 r0, float4 r1,
                                      float ev, float4 w0, float4 w1,
                                      float4 t0, float4 t1){
    float p = 0.f;
    p += lrelu(l0.x + r0.x + ev*w0.x) * t0.x;
    p += lrelu(l0.y + r0.y + ev*w0.y) * t0.y;
    p += lrelu(l0.z + r0.z + ev*w0.z) * t0.z;
    p += lrelu(l0.w + r0.w + ev*w0.w) * t0.w;
    p += lrelu(l1.x + r1.x + ev*w1.x) * t1.x;
    p += lrelu(l1.y + r1.y + ev*w1.y) * t1.y;
    p += lrelu(l1.z + r1.z + ev*w1.z) * t1.z;
    p += lrelu(l1.w + r1.w + ev*w1.w) * t1.w;
    return p;
}

// ---------------- init ----------------
__global__ void k_init(){
    int i = blockIdx.x*blockDim.x + threadIdx.x;
    if(i < Nn){ g_deg[i] = 0.f; g_loop[i] = 0.f; }
    if(i < Nn*4){ g_mx[i] = ENC_NEG_INF; g_den[i] = 0.f; }
    if(i < Nn*HID) g_acc[i] = 0.f;
}
__global__ void k_reinit(){
    int i = blockIdx.x*blockDim.x + threadIdx.x;
    if(i < Nn*4){ g_mx[i] = ENC_NEG_INF; g_den[i] = 0.f; }
    if(i < Nn*HID) g_acc[i] = 0.f;
}

// ---------------- self-loop attr (mean of incoming edge_attr) ----------------
__global__ void k_degloop(const int* __restrict__ dst, const float* __restrict__ ea){
    int e = blockIdx.x*blockDim.x + threadIdx.x;
    if(e < Ne){
        int d = dst[e];
        atomicAdd(&g_deg[d], 1.f);
        atomicAdd(&g_loop[d], ea[e]);
    }
}
__global__ void k_loopdiv(){
    int i = blockIdx.x*blockDim.x + threadIdx.x;
    if(i < Nn) g_loop[i] = g_loop[i] / fmaxf(g_deg[i], 1.f);
}

// ---------------- conv1 linear (IN=4 -> 256, both lin_l and lin_r) ----------------
__global__ void k_lin1(const float* __restrict__ x,
                       const float* __restrict__ Wl, const float* __restrict__ bl,
                       const float* __restrict__ Wr, const float* __restrict__ br){
    int t = blockIdx.x*blockDim.x + threadIdx.x;
    if(t >= Nn*HID) return;
    int n = t >> 8, c = t & 255;
    float x0 = x[n*4+0], x1 = x[n*4+1], x2 = x[n*4+2], x3 = x[n*4+3];
    float l = bl[c] + x0*Wl[c] + x1*Wl[256+c] + x2*Wl[512+c] + x3*Wl[768+c];
    float r = br[c] + x0*Wr[c] + x1*Wr[256+c] + x2*Wr[512+c] + x3*Wr[768+c];
    g_xl[t] = l; g_xr[t] = r;
}

// ---------------- conv1 edge pass A: logits (H=4, C=64) ----------------
__global__ void k_edgeA1(const int* __restrict__ src, const int* __restrict__ dst,
                         const float* __restrict__ ea,
                         const float* __restrict__ We, const float* __restrict__ att){
    int w = (blockIdx.x*blockDim.x + threadIdx.x) >> 5;
    int lane = threadIdx.x & 31;
    if(w >= EAt) return;
    int s, d; float ev;
    if(w < Ne){ s = src[w]; d = dst[w]; ev = ea[w]; }
    else      { s = w - Ne; d = s; ev = g_loop[s]; }
    int c0 = lane * 8;
    const float4* pl = (const float4*)(g_xl + s*HID + c0);
    const float4* pr = (const float4*)(g_xr + d*HID + c0);
    const float4* pw = (const float4*)(We  + c0);
    const float4* pa = (const float4*)(att + c0);
    float p = dot8(pl[0], pl[1], pr[0], pr[1], ev, pw[0], pw[1], pa[0], pa[1]);
    // reduce within groups of 8 lanes (one head per group)
    p += __shfl_xor_sync(0xffffffffu, p, 1);
    p += __shfl_xor_sync(0xffffffffu, p, 2);
    p += __shfl_xor_sync(0xffffffffu, p, 4);
    if((lane & 7) == 0){
        int h = lane >> 3;
        g_logit[w*4 + h] = p;
        atomicMax(&g_mx[d*4 + h], encf(p));
    }
}

// ---------------- conv1 edge pass B: exp, denominators, weighted scatter ----------------
__global__ void k_edgeB1(const int* __restrict__ src, const int* __restrict__ dst){
    int w = (blockIdx.x*blockDim.x + threadIdx.x) >> 5;
    int lane = threadIdx.x & 31;
    if(w >= EAt) return;
    int s, d;
    if(w < Ne){ s = src[w]; d = dst[w]; }
    else      { s = w - Ne; d = s; }
    int c0 = lane * 8;
    int h = lane >> 3;
    float lg = g_logit[w*4 + h];
    float mx = decf(g_mx[d*4 + h]);
    float ex = expf(lg - mx);
    if((lane & 7) == 0) atomicAdd(&g_den[d*4 + h], ex);
    const float4* pl = (const float4*)(g_xl + s*HID + c0);
    float4 l0 = pl[0], l1 = pl[1];
    float* base = g_acc + d*HID + c0;
    red4(base,     l0.x*ex, l0.y*ex, l0.z*ex, l0.w*ex);
    red4(base + 4, l1.x*ex, l1.y*ex, l1.z*ex, l1.w*ex);
}

// ---------------- conv1 node pass: normalize + bias + LayerNorm + ReLU ----------------
__global__ void k_nodeC1(const float* __restrict__ bias, const float* __restrict__ gam,
                         const float* __restrict__ bet){
    int n = (blockIdx.x*blockDim.x + threadIdx.x) >> 5;
    int lane = threadIdx.x & 31;
    if(n >= Nn) return;
    int c0 = lane * 8;
    int h = c0 >> 6;
    float inv = 1.f / g_den[n*4 + h];
    float4 a0 = *(const float4*)(g_acc + n*HID + c0);
    float4 a1 = *(const float4*)(g_acc + n*HID + c0 + 4);
    float v[8] = {a0.x,a0.y,a0.z,a0.w,a1.x,a1.y,a1.z,a1.w};
    float s = 0.f;
    #pragma unroll
    for(int i = 0; i < 8; i++){ v[i] = v[i]*inv + bias[c0+i]; s += v[i]; }
    #pragma unroll
    for(int o = 16; o; o >>= 1) s += __shfl_xor_sync(0xffffffffu, s, o);
    float mu = s * (1.f/256.f);
    float q = 0.f;
    #pragma unroll
    for(int i = 0; i < 8; i++){ float dd = v[i]-mu; q += dd*dd; }
    #pragma unroll
    for(int o = 16; o; o >>= 1) q += __shfl_xor_sync(0xffffffffu, q, o);
    float rstd = rsqrtf(q*(1.f/256.f) + 1e-5f);
    float o0[8];
    #pragma unroll
    for(int i = 0; i < 8; i++)
        o0[i] = fmaxf((v[i]-mu)*rstd*gam[c0+i] + bet[c0+i], 0.f);
    *(float4*)(g_h + n*HID + c0)     = make_float4(o0[0],o0[1],o0[2],o0[3]);
    *(float4*)(g_h + n*HID + c0 + 4) = make_float4(o0[4],o0[5],o0[6],o0[7]);
}

// ---------------- tiled fp32 GEMM: C = A(g_h)[Nn,K] @ B[K,Nc] + bias, opt ReLU --------
__global__ void k_gemm(const float* __restrict__ B, const float* __restrict__ bias,
                       int K, int Nc, int relu, int outsel){
    __shared__ __align__(16) float As[16][68];
    __shared__ __align__(16) float Bs[16][68];
    const float* A = g_h;
    float* C = (outsel == 0) ? g_xl : (outsel == 1) ? g_xr : g_p1;
    int m0 = blockIdx.y*64, n0 = blockIdx.x*64;
    int t = threadIdx.x;
    int tx = t & 15, ty = t >> 4;
    float acc[4][4] = {};
    int arow = t >> 2, ak = (t & 3) * 4;
    int brow = t >> 4, bc = (t & 15) * 4;
    for(int k0 = 0; k0 < K; k0 += 16){
        float4 av = make_float4(0.f,0.f,0.f,0.f);
        int gm = m0 + arow;
        if(gm < Nn) av = *(const float4*)(A + gm*K + k0 + ak);
        As[ak+0][arow] = av.x; As[ak+1][arow] = av.y;
        As[ak+2][arow] = av.z; As[ak+3][arow] = av.w;
        *(float4*)&Bs[brow][bc] = *(const float4*)(B + (k0+brow)*Nc + n0 + bc);
        __syncthreads();
        #pragma unroll
        for(int kk = 0; kk < 16; kk++){
            float4 a = *(float4*)&As[kk][ty*4];
            float4 b = *(float4*)&Bs[kk][tx*4];
            acc[0][0]+=a.x*b.x; acc[0][1]+=a.x*b.y; acc[0][2]+=a.x*b.z; acc[0][3]+=a.x*b.w;
            acc[1][0]+=a.y*b.x; acc[1][1]+=a.y*b.y; acc[1][2]+=a.y*b.z; acc[1][3]+=a.y*b.w;
            acc[2][0]+=a.z*b.x; acc[2][1]+=a.z*b.y; acc[2][2]+=a.z*b.z; acc[2][3]+=a.z*b.w;
            acc[3][0]+=a.w*b.x; acc[3][1]+=a.w*b.y; acc[3][2]+=a.w*b.z; acc[3][3]+=a.w*b.w;
        }
        __syncthreads();
    }
    #pragma unroll
    for(int i = 0; i < 4; i++){
        int gm = m0 + ty*4 + i;
        if(gm >= Nn) continue;
        #pragma unroll
        for(int j = 0; j < 4; j++){
            int col = n0 + tx*4 + j;
            float v = acc[i][j] + bias[col];
            if(relu) v = fmaxf(v, 0.f);
            C[gm*Nc + col] = v;
        }
    }
}

// ---------------- conv2 edge pass A: logits (H=1, C=256) ----------------
__global__ void k_edgeA2(const int* __restrict__ src, const int* __restrict__ dst,
                         const float* __restrict__ ea,
                         const float* __restrict__ We, const float* __restrict__ att){
    int w = (blockIdx.x*blockDim.x + threadIdx.x) >> 5;
    int lane = threadIdx.x & 31;
    if(w >= EAt) return;
    int s, d; float ev;
    if(w < Ne){ s = src[w]; d = dst[w]; ev = ea[w]; }
    else      { s = w - Ne; d = s; ev = g_loop[s]; }
    int c0 = lane * 8;
    const float4* pl = (const float4*)(g_xl + s*HID + c0);
    const float4* pr = (const float4*)(g_xr + d*HID + c0);
    const float4* pw = (const float4*)(We  + c0);
    const float4* pa = (const float4*)(att + c0);
    float p = dot8(pl[0], pl[1], pr[0], pr[1], ev, pw[0], pw[1], pa[0], pa[1]);
    #pragma unroll
    for(int o = 1; o < 32; o <<= 1) p += __shfl_xor_sync(0xffffffffu, p, o);
    if(lane == 0){
        g_logit[w] = p;
        atomicMax(&g_mx[d], encf(p));
    }
}

// ---------------- conv2 edge pass B ----------------
__global__ void k_edgeB2(const int* __restrict__ src, const int* __restrict__ dst){
    int w = (blockIdx.x*blockDim.x + threadIdx.x) >> 5;
    int lane = threadIdx.x & 31;
    if(w >= EAt) return;
    int s, d;
    if(w < Ne){ s = src[w]; d = dst[w]; }
    else      { s = w - Ne; d = s; }
    float ex = expf(g_logit[w] - decf(g_mx[d]));
    if(lane == 0) atomicAdd(&g_den[d], ex);
    int c0 = lane * 8;
    const float4* pl = (const float4*)(g_xl + s*HID + c0);
    float4 l0 = pl[0], l1 = pl[1];
    float* base = g_acc + d*HID + c0;
    red4(base,     l0.x*ex, l0.y*ex, l0.z*ex, l0.w*ex);
    red4(base + 4, l1.x*ex, l1.y*ex, l1.z*ex, l1.w*ex);
}

// ---------------- conv2 node pass ----------------
__global__ void k_nodeC2(const float* __restrict__ bias, const float* __restrict__ gam,
                         const float* __restrict__ bet){
    int n = (blockIdx.x*blockDim.x + threadIdx.x) >> 5;
    int lane = threadIdx.x & 31;
    if(n >= Nn) return;
    int c0 = lane * 8;
    float inv = 1.f / g_den[n];
    float4 a0 = *(const float4*)(g_acc + n*HID + c0);
    float4 a1 = *(const float4*)(g_acc + n*HID + c0 + 4);
    float v[8] = {a0.x,a0.y,a0.z,a0.w,a1.x,a1.y,a1.z,a1.w};
    float s = 0.f;
    #pragma unroll
    for(int i = 0; i < 8; i++){ v[i] = v[i]*inv + bias[c0+i]; s += v[i]; }
    #pragma unroll
    for(int o = 16; o; o >>= 1) s += __shfl_xor_sync(0xffffffffu, s, o);
    float mu = s * (1.f/256.f);
    float q = 0.f;
    #pragma unroll
    for(int i = 0; i < 8; i++){ float dd = v[i]-mu; q += dd*dd; }
    #pragma unroll
    for(int o = 16; o; o >>= 1) q += __shfl_xor_sync(0xffffffffu, q, o);
    float rstd = rsqrtf(q*(1.f/256.f) + 1e-5f);
    float o0[8];
    #pragma unroll
    for(int i = 0; i < 8; i++)
        o0[i] = fmaxf((v[i]-mu)*rstd*gam[c0+i] + bet[c0+i], 0.f);
    *(float4*)(g_h + n*HID + c0)     = make_float4(o0[0],o0[1],o0[2],o0[3]);
    *(float4*)(g_h + n*HID + c0 + 4) = make_float4(o0[4],o0[5],o0[6],o0[7]);
}

// ---------------- policy head final linear: [Nn,128] @ [128,4] ----------------
__global__ void k_lin3(const float* __restrict__ Wp2, const float* __restrict__ bp2){
    int t = blockIdx.x*blockDim.x + threadIdx.x;
    if(t >= Nn*4) return;
    int n = t >> 2, c = t & 3;
    const float* pr = g_p1 + n*128;
    float s = bp2[c];
    #pragma unroll 16
    for(int k = 0; k < 128; k++) s += pr[k]*Wp2[k*4 + c];
    g_pl[t] = s;
}

// ---------------- global softmax (40000 logits) ----------------
__global__ void k_reduce(){
    __shared__ float sm[1024];
    int tid = threadIdx.x;
    float m = -3.4e38f;
    for(int i = tid; i < Nn*4; i += 1024) m = fmaxf(m, g_pl[i]);
    sm[tid] = m; __syncthreads();
    for(int o = 512; o > 0; o >>= 1){ if(tid < o) sm[tid] = fmaxf(sm[tid], sm[tid+o]); __syncthreads(); }
    float mx = sm[0]; __syncthreads();
    float s = 0.f;
    for(int i = tid; i < Nn*4; i += 1024) s += expf(g_pl[i] - mx);
    sm[tid] = s; __syncthreads();
    for(int o = 512; o > 0; o >>= 1){ if(tid < o) sm[tid] += sm[tid+o]; __syncthreads(); }
    if(tid == 0){ g_red[0] = mx; g_red[1] = sm[0]; }
}
__global__ void k_out(float* __restrict__ out){
    int i = blockIdx.x*blockDim.x + threadIdx.x;
    if(i < Nn*4) out[i] = expf(g_pl[i] - g_red[0]) / g_red[1];
}

// ---------------- launch ----------------
extern "C" void kernel_launch(void* const* d_in, const int* in_sizes, int n_in,
                              void* d_out, int out_size){
    const float* x     = (const float*)d_in[0];
    const int*   ei    = (const int*)  d_in[1];
    const float* ea    = (const float*)d_in[2];
    const float* Wl1   = (const float*)d_in[3];
    const float* bl1   = (const float*)d_in[4];
    const float* Wr1   = (const float*)d_in[5];
    const float* br1   = (const float*)d_in[6];
    const float* We1   = (const float*)d_in[7];
    const float* att1  = (const float*)d_in[8];
    const float* bias1 = (const float*)d_in[9];
    const float* g1    = (const float*)d_in[10];
    const float* be1   = (const float*)d_in[11];
    const float* Wl2   = (const float*)d_in[12];
    const float* bl2   = (const float*)d_in[13];
    const float* Wr2   = (const float*)d_in[14];
    const float* br2   = (const float*)d_in[15];
    const float* We2   = (const float*)d_in[16];
    const float* att2  = (const float*)d_in[17];
    const float* bias2 = (const float*)d_in[18];
    const float* g2    = (const float*)d_in[19];
    const float* be2   = (const float*)d_in[20];
    const float* Wp1   = (const float*)d_in[21];
    const float* bp1   = (const float*)d_in[22];
    const float* Wp2   = (const float*)d_in[23];
    const float* bp2   = (const float*)d_in[24];
    const int* src = ei;
    const int* dst = ei + Ne;
    float* out = (float*)d_out;

    const int TB = 256;
    int gridNodeFeat = (Nn*HID + TB-1)/TB;
    int gridEdgeWarp = (EAt*32 + TB-1)/TB;
    int gridNodeWarp = (Nn*32 + TB-1)/TB;

    // init + self-loop edge_attr
    k_init<<<gridNodeFeat, TB>>>();
    k_degloop<<<(Ne+TB-1)/TB, TB>>>(dst, ea);
    k_loopdiv<<<(Nn+TB-1)/TB, TB>>>();

    // conv1
    k_lin1<<<gridNodeFeat, TB>>>(x, Wl1, bl1, Wr1, br1);
    k_edgeA1<<<gridEdgeWarp, TB>>>(src, dst, ea, We1, att1);
    k_edgeB1<<<gridEdgeWarp, TB>>>(src, dst);
    k_nodeC1<<<gridNodeWarp, TB>>>(bias1, g1, be1);

    // conv2
    k_reinit<<<gridNodeFeat, TB>>>();
    k_gemm<<<dim3(4, (Nn+63)/64), 256>>>(Wl2, bl2, 256, 256, 0, 0);  // g_xl = h1@Wl2+bl2
    k_gemm<<<dim3(4, (Nn+63)/64), 256>>>(Wr2, br2, 256, 256, 0, 1);  // g_xr = h1@Wr2+br2
    k_edgeA2<<<gridEdgeWarp, TB>>>(src, dst, ea, We2, att2);
    k_edgeB2<<<gridEdgeWarp, TB>>>(src, dst);
    k_nodeC2<<<gridNodeWarp, TB>>>(bias2, g2, be2);

    // policy head
    k_gemm<<<dim3(2, (Nn+63)/64), 256>>>(Wp1, bp1, 256, 128, 1, 2);  // g_p1 = relu(h2@Wp1+bp1)
    k_lin3<<<(Nn*4+TB-1)/TB, TB>>>(Wp2, bp2);

    // global softmax
    k_reduce<<<1, 1024>>>();
    k_out<<<(Nn*4+TB-1)/TB, TB>>>(out);
}

// round 2
// speedup vs baseline: 1.8618x; 1.8618x over previous
#include <cuda_runtime.h>

#define Nn   10000
#define Ne   320000
#define EAt  330000      // edges + self loops
#define HID  256

// ---------------- scratch (static device globals; no allocation) ----------------
__device__ float    g_loop[Nn];
__device__ int      g_cnt[Nn];
__device__ int      g_row[Nn+1];
__device__ int      g_woff[Nn];
__device__ int      g_csrc[EAt];
__device__ float    g_cea[EAt];
__device__ float    g_xl[Nn*HID];
__device__ float    g_xr[Nn*HID];
__device__ float    g_h[Nn*HID];
__device__ float    g_p1[Nn*128];
__device__ float    g_pl[Nn*4];
__device__ float    g_red[2];

__device__ __forceinline__ float lrelu(float v){ return v > 0.f ? v : 0.2f * v; }

__device__ __forceinline__ float dot8(float4 l0, float4 l1, float4 r0, float4 r1,
                                      float ev, float4 w0, float4 w1,
                                      float4 t0, float4 t1){
    float p = 0.f;
    p += lrelu(l0.x + r0.x + ev*w0.x) * t0.x;
    p += lrelu(l0.y + r0.y + ev*w0.y) * t0.y;
    p += lrelu(l0.z + r0.z + ev*w0.z) * t0.z;
    p += lrelu(l0.w + r0.w + ev*w0.w) * t0.w;
    p += lrelu(l1.x + r1.x + ev*w1.x) * t1.x;
    p += lrelu(l1.y + r1.y + ev*w1.y) * t1.y;
    p += lrelu(l1.z + r1.z + ev*w1.z) * t1.z;
    p += lrelu(l1.w + r1.w + ev*w1.w) * t1.w;
    return p;
}

// ---------------- CSR build ----------------
__global__ void k_z(){
    int i = blockIdx.x*blockDim.x + threadIdx.x;
    if(i < Nn){ g_cnt[i] = 0; g_loop[i] = 0.f; }
}
__global__ void k_hist(const int* __restrict__ dst, const float* __restrict__ ea){
    int e = blockIdx.x*blockDim.x + threadIdx.x;
    if(e < Ne){
        int d = dst[e];
        atomicAdd(&g_cnt[d], 1);
        atomicAdd(&g_loop[d], ea[e]);
    }
}
// exclusive scan of (cnt[i]+1) over 10000 entries, single block of 1024
__global__ void k_scan(){
    __shared__ int part[1024];
    const int NP = 10;
    int tid = threadIdx.x;
    int base = tid * NP;
    int loc[NP];
    int s = 0;
    #pragma unroll
    for(int i = 0; i < NP; i++){
        int idx = base + i;
        int v = (idx < Nn) ? (g_cnt[idx] + 1) : 0;
        loc[i] = s; s += v;
    }
    part[tid] = s; __syncthreads();
    for(int o = 1; o < 1024; o <<= 1){
        int v = (tid >= o) ? part[tid - o] : 0;
        __syncthreads();
        if(tid >= o) part[tid] += v;
        __syncthreads();
    }
    int off = (tid > 0) ? part[tid - 1] : 0;
    #pragma unroll
    for(int i = 0; i < NP; i++){
        int idx = base + i;
        if(idx <= Nn) g_row[idx] = off + loc[i];
    }
}
// finalize loop attr, place self-loop at end of each row, init write offsets
__global__ void k_prep(){
    int i = blockIdx.x*blockDim.x + threadIdx.x;
    if(i >= Nn) return;
    int c = g_cnt[i];
    float lp = g_loop[i] / fmaxf((float)c, 1.f);
    g_loop[i] = lp;
    int e = g_row[i+1] - 1;
    g_csrc[e] = i;
    g_cea[e] = lp;
    g_woff[i] = g_row[i];
}
__global__ void k_scatter(const int* __restrict__ src, const int* __restrict__ dst,
                          const float* __restrict__ ea){
    int e = blockIdx.x*blockDim.x + threadIdx.x;
    if(e >= Ne) return;
    int d = dst[e];
    int pos = atomicAdd(&g_woff[d], 1);
    g_csrc[pos] = src[e];
    g_cea[pos] = ea[e];
}

// ---------------- conv1 linear (IN=4 -> 256) ----------------
__global__ void k_lin1(const float* __restrict__ x,
                       const float* __restrict__ Wl, const float* __restrict__ bl,
                       const float* __restrict__ Wr, const float* __restrict__ br){
    int t = blockIdx.x*blockDim.x + threadIdx.x;
    if(t >= Nn*HID) return;
    int n = t >> 8, c = t & 255;
    float x0 = x[n*4+0], x1 = x[n*4+1], x2 = x[n*4+2], x3 = x[n*4+3];
    float l = bl[c] + x0*Wl[c] + x1*Wl[256+c] + x2*Wl[512+c] + x3*Wl[768+c];
    float r = br[c] + x0*Wr[c] + x1*Wr[256+c] + x2*Wr[512+c] + x3*Wr[768+c];
    g_xl[t] = l; g_xr[t] = r;
}

// ---------------- fused conv1: gather + online softmax + LN + ReLU (warp/node) ----
__global__ void k_conv1(const float* __restrict__ We, const float* __restrict__ att,
                        const float* __restrict__ bias, const float* __restrict__ gam,
                        const float* __restrict__ bet){
    int n = (blockIdx.x*blockDim.x + threadIdx.x) >> 5;
    int lane = threadIdx.x & 31;
    if(n >= Nn) return;
    int c0 = lane * 8;
    const float4* pr = (const float4*)(g_xr + n*HID + c0);
    float4 r0 = pr[0], r1 = pr[1];
    float4 w0 = *(const float4*)(We + c0),  w1 = *(const float4*)(We + c0 + 4);
    float4 t0 = *(const float4*)(att + c0), t1 = *(const float4*)(att + c0 + 4);
    float acc[8] = {0,0,0,0,0,0,0,0};
    float den = 0.f, mx = -1e30f;
    int b = g_row[n], e = g_row[n+1];
    for(int i = b; i < e; i++){
        int s = g_csrc[i];
        float ev = g_cea[i];
        const float4* pl = (const float4*)(g_xl + s*HID + c0);
        float4 l0 = pl[0], l1 = pl[1];
        float p = dot8(l0, l1, r0, r1, ev, w0, w1, t0, t1);
        p += __shfl_xor_sync(0xffffffffu, p, 1);
        p += __shfl_xor_sync(0xffffffffu, p, 2);
        p += __shfl_xor_sync(0xffffffffu, p, 4);
        float nm = fmaxf(mx, p);
        float f  = __expf(mx - nm);
        float ex = __expf(p - nm);
        den = den * f + ex;
        mx = nm;
        acc[0] = acc[0]*f + l0.x*ex; acc[1] = acc[1]*f + l0.y*ex;
        acc[2] = acc[2]*f + l0.z*ex; acc[3] = acc[3]*f + l0.w*ex;
        acc[4] = acc[4]*f + l1.x*ex; acc[5] = acc[5]*f + l1.y*ex;
        acc[6] = acc[6]*f + l1.z*ex; acc[7] = acc[7]*f + l1.w*ex;
    }
    float inv = 1.f / den;
    float v[8];
    float s = 0.f;
    #pragma unroll
    for(int i = 0; i < 8; i++){ v[i] = acc[i]*inv + bias[c0+i]; s += v[i]; }
    #pragma unroll
    for(int o = 16; o; o >>= 1) s += __shfl_xor_sync(0xffffffffu, s, o);
    float mu = s * (1.f/256.f);
    float q = 0.f;
    #pragma unroll
    for(int i = 0; i < 8; i++){ float dd = v[i]-mu; q += dd*dd; }
    #pragma unroll
    for(int o = 16; o; o >>= 1) q += __shfl_xor_sync(0xffffffffu, q, o);
    float rstd = rsqrtf(q*(1.f/256.f) + 1e-5f);
    float o0[8];
    #pragma unroll
    for(int i = 0; i < 8; i++)
        o0[i] = fmaxf((v[i]-mu)*rstd*gam[c0+i] + bet[c0+i], 0.f);
    *(float4*)(g_h + n*HID + c0)     = make_float4(o0[0],o0[1],o0[2],o0[3]);
    *(float4*)(g_h + n*HID + c0 + 4) = make_float4(o0[4],o0[5],o0[6],o0[7]);
}

// ---------------- fused conv2 (H=1, C=256) ----------------
__global__ void k_conv2(const float* __restrict__ We, const float* __restrict__ att,
                        const float* __restrict__ bias, const float* __restrict__ gam,
                        const float* __restrict__ bet){
    int n = (blockIdx.x*blockDim.x + threadIdx.x) >> 5;
    int lane = threadIdx.x & 31;
    if(n >= Nn) return;
    int c0 = lane * 8;
    const float4* pr = (const float4*)(g_xr + n*HID + c0);
    float4 r0 = pr[0], r1 = pr[1];
    float4 w0 = *(const float4*)(We + c0),  w1 = *(const float4*)(We + c0 + 4);
    float4 t0 = *(const float4*)(att + c0), t1 = *(const float4*)(att + c0 + 4);
    float acc[8] = {0,0,0,0,0,0,0,0};
    float den = 0.f, mx = -1e30f;
    int b = g_row[n], e = g_row[n+1];
    for(int i = b; i < e; i++){
        int s = g_csrc[i];
        float ev = g_cea[i];
        const float4* pl = (const float4*)(g_xl + s*HID + c0);
        float4 l0 = pl[0], l1 = pl[1];
        float p = dot8(l0, l1, r0, r1, ev, w0, w1, t0, t1);
        #pragma unroll
        for(int o = 1; o < 32; o <<= 1) p += __shfl_xor_sync(0xffffffffu, p, o);
        float nm = fmaxf(mx, p);
        float f  = __expf(mx - nm);
        float ex = __expf(p - nm);
        den = den * f + ex;
        mx = nm;
        acc[0] = acc[0]*f + l0.x*ex; acc[1] = acc[1]*f + l0.y*ex;
        acc[2] = acc[2]*f + l0.z*ex; acc[3] = acc[3]*f + l0.w*ex;
        acc[4] = acc[4]*f + l1.x*ex; acc[5] = acc[5]*f + l1.y*ex;
        acc[6] = acc[6]*f + l1.z*ex; acc[7] = acc[7]*f + l1.w*ex;
    }
    float inv = 1.f / den;
    float v[8];
    float s = 0.f;
    #pragma unroll
    for(int i = 0; i < 8; i++){ v[i] = acc[i]*inv + bias[c0+i]; s += v[i]; }
    #pragma unroll
    for(int o = 16; o; o >>= 1) s += __shfl_xor_sync(0xffffffffu, s, o);
    float mu = s * (1.f/256.f);
    float q = 0.f;
    #pragma unroll
    for(int i = 0; i < 8; i++){ float dd = v[i]-mu; q += dd*dd; }
    #pragma unroll
    for(int o = 16; o; o >>= 1) q += __shfl_xor_sync(0xffffffffu, q, o);
    float rstd = rsqrtf(q*(1.f/256.f) + 1e-5f);
    float o0[8];
    #pragma unroll
    for(int i = 0; i < 8; i++)
        o0[i] = fmaxf((v[i]-mu)*rstd*gam[c0+i] + bet[c0+i], 0.f);
    *(float4*)(g_h + n*HID + c0)     = make_float4(o0[0],o0[1],o0[2],o0[3]);
    *(float4*)(g_h + n*HID + c0 + 4) = make_float4(o0[4],o0[5],o0[6],o0[7]);
}

// ---------------- tiled fp32 GEMM: C = g_h[Nn,K] @ B[K,Nc] + bias, opt ReLU ------
__global__ void k_gemm(const float* __restrict__ B, const float* __restrict__ bias,
                       int K, int Nc, int relu, int outsel){
    __shared__ __align__(16) float As[16][68];
    __shared__ __align__(16) float Bs[16][68];
    const float* A = g_h;
    float* C = (outsel == 0) ? g_xl : (outsel == 1) ? g_xr : g_p1;
    int m0 = blockIdx.y*64, n0 = blockIdx.x*64;
    int t = threadIdx.x;
    int tx = t & 15, ty = t >> 4;
    float acc[4][4] = {};
    int arow = t >> 2, ak = (t & 3) * 4;
    int brow = t >> 4, bc = (t & 15) * 4;
    for(int k0 = 0; k0 < K; k0 += 16){
        float4 av = make_float4(0.f,0.f,0.f,0.f);
        int gm = m0 + arow;
        if(gm < Nn) av = *(const float4*)(A + gm*K + k0 + ak);
        As[ak+0][arow] = av.x; As[ak+1][arow] = av.y;
        As[ak+2][arow] = av.z; As[ak+3][arow] = av.w;
        *(float4*)&Bs[brow][bc] = *(const float4*)(B + (k0+brow)*Nc + n0 + bc);
        __syncthreads();
        #pragma unroll
        for(int kk = 0; kk < 16; kk++){
            float4 a = *(float4*)&As[kk][ty*4];
            float4 b = *(float4*)&Bs[kk][tx*4];
            acc[0][0]+=a.x*b.x; acc[0][1]+=a.x*b.y; acc[0][2]+=a.x*b.z; acc[0][3]+=a.x*b.w;
            acc[1][0]+=a.y*b.x; acc[1][1]+=a.y*b.y; acc[1][2]+=a.y*b.z; acc[1][3]+=a.y*b.w;
            acc[2][0]+=a.z*b.x; acc[2][1]+=a.z*b.y; acc[2][2]+=a.z*b.z; acc[2][3]+=a.z*b.w;
            acc[3][0]+=a.w*b.x; acc[3][1]+=a.w*b.y; acc[3][2]+=a.w*b.z; acc[3][3]+=a.w*b.w;
        }
        __syncthreads();
    }
    #pragma unroll
    for(int i = 0; i < 4; i++){
        int gm = m0 + ty*4 + i;
        if(gm >= Nn) continue;
        #pragma unroll
        for(int j = 0; j < 4; j++){
            int col = n0 + tx*4 + j;
            float v = acc[i][j] + bias[col];
            if(relu) v = fmaxf(v, 0.f);
            C[gm*Nc + col] = v;
        }
    }
}

// ---------------- policy head final linear: [Nn,128] @ [128,4] ----------------
__global__ void k_lin3(const float* __restrict__ Wp2, const float* __restrict__ bp2){
    int t = blockIdx.x*blockDim.x + threadIdx.x;
    if(t >= Nn*4) return;
    int n = t >> 2, c = t & 3;
    const float* pr = g_p1 + n*128;
    float s = bp2[c];
    #pragma unroll 16
    for(int k = 0; k < 128; k++) s += pr[k]*Wp2[k*4 + c];
    g_pl[t] = s;
}

// ---------------- global softmax (40000 logits) ----------------
__global__ void k_reduce(){
    __shared__ float sm[1024];
    int tid = threadIdx.x;
    float m = -3.4e38f;
    for(int i = tid; i < Nn*4; i += 1024) m = fmaxf(m, g_pl[i]);
    sm[tid] = m; __syncthreads();
    for(int o = 512; o > 0; o >>= 1){ if(tid < o) sm[tid] = fmaxf(sm[tid], sm[tid+o]); __syncthreads(); }
    float mx = sm[0]; __syncthreads();
    float s = 0.f;
    for(int i = tid; i < Nn*4; i += 1024) s += expf(g_pl[i] - mx);
    sm[tid] = s; __syncthreads();
    for(int o = 512; o > 0; o >>= 1){ if(tid < o) sm[tid] += sm[tid+o]; __syncthreads(); }
    if(tid == 0){ g_red[0] = mx; g_red[1] = sm[0]; }
}
__global__ void k_out(float* __restrict__ out){
    int i = blockIdx.x*blockDim.x + threadIdx.x;
    if(i < Nn*4) out[i] = expf(g_pl[i] - g_red[0]) / g_red[1];
}

// ---------------- launch ----------------
extern "C" void kernel_launch(void* const* d_in, const int* in_sizes, int n_in,
                              void* d_out, int out_size){
    const float* x     = (const float*)d_in[0];
    const int*   ei    = (const int*)  d_in[1];
    const float* ea    = (const float*)d_in[2];
    const float* Wl1   = (const float*)d_in[3];
    const float* bl1   = (const float*)d_in[4];
    const float* Wr1   = (const float*)d_in[5];
    const float* br1   = (const float*)d_in[6];
    const float* We1   = (const float*)d_in[7];
    const float* att1  = (const float*)d_in[8];
    const float* bias1 = (const float*)d_in[9];
    const float* g1    = (const float*)d_in[10];
    const float* be1   = (const float*)d_in[11];
    const float* Wl2   = (const float*)d_in[12];
    const float* bl2   = (const float*)d_in[13];
    const float* Wr2   = (const float*)d_in[14];
    const float* br2   = (const float*)d_in[15];
    const float* We2   = (const float*)d_in[16];
    const float* att2  = (const float*)d_in[17];
    const float* bias2 = (const float*)d_in[18];
    const float* g2    = (const float*)d_in[19];
    const float* be2   = (const float*)d_in[20];
    const float* Wp1   = (const float*)d_in[21];
    const float* bp1   = (const float*)d_in[22];
    const float* Wp2   = (const float*)d_in[23];
    const float* bp2   = (const float*)d_in[24];
    const int* src = ei;
    const int* dst = ei + Ne;
    float* out = (float*)d_out;

    const int TB = 256;

    // CSR build (shared by both convs)
    k_z<<<(Nn+TB-1)/TB, TB>>>();
    k_hist<<<(Ne+TB-1)/TB, TB>>>(dst, ea);
    k_scan<<<1, 1024>>>();
    k_prep<<<(Nn+TB-1)/TB, TB>>>();
    k_scatter<<<(Ne+TB-1)/TB, TB>>>(src, dst, ea);

    // conv1
    k_lin1<<<(Nn*HID+TB-1)/TB, TB>>>(x, Wl1, bl1, Wr1, br1);
    k_conv1<<<(Nn*32+TB-1)/TB, TB>>>(We1, att1, bias1, g1, be1);

    // conv2
    k_gemm<<<dim3(4, (Nn+63)/64), 256>>>(Wl2, bl2, 256, 256, 0, 0);
    k_gemm<<<dim3(4, (Nn+63)/64), 256>>>(Wr2, br2, 256, 256, 0, 1);
    k_conv2<<<(Nn*32+TB-1)/TB, TB>>>(We2, att2, bias2, g2, be2);

    // policy head
    k_gemm<<<dim3(2, (Nn+63)/64), 256>>>(Wp1, bp1, 256, 128, 1, 2);
    k_lin3<<<(Nn*4+TB-1)/TB, TB>>>(Wp2, bp2);

    // global softmax
    k_reduce<<<1, 1024>>>();
    k_out<<<(Nn*4+TB-1)/TB, TB>>>(out);
}